// round 14
// baseline (speedup 1.0000x reference)
#include <cuda_runtime.h>
#include <cuda_fp16.h>
#include <cstdint>

// ---------------- problem constants ----------------
#define Bb 8
#define Tt 4096
#define Pp 256
#define Mm 32768
#define Kx 512
#define Nn 768            // angles 256 + inj 512
#define TILE_M 128
#define TILE_N 128
#define NTHREADS 256
#define KC 64             // k-chunk (64 fp16 = 128B rows)
#define NCHUNK (Kx / KC)  // 8
#define NSTAGES 3
#define CHUNK_BYTES 16384               // 128 rows x 128B, pre-swizzled
#define A_BYTES CHUNK_BYTES
#define B_BYTES CHUNK_BYTES
#define STAGE_BYTES (A_BYTES + B_BYTES) // 32768
#define DYN_BYTES (NSTAGES * STAGE_BYTES)   // 98304 -> 2 CTAs/SM
#define NMT (Mm / TILE_M)     // 256 m-tiles
#define NNT (Nn / TILE_N)     // 6 n-tiles
#define NTILES (NMT * NNT)    // 1536

// scan chunking
#define SCHUNK 32
#define NCH (Tt / SCHUNK)         // 128

// ---------------- device scratch (no allocation) ----------------
__device__ __align__(128) char g_At[(size_t)NMT * NCHUNK * CHUNK_BYTES];
__device__ __align__(128) char g_Bt[(size_t)NNT * NCHUNK * CHUNK_BYTES];
__device__ float    g_bcat[Nn];
__device__ __half2  g_cs[(size_t)Mm * Pp];      // packed (cos, sin), fp16
__device__ __half2  g_u[(size_t)Mm * Pp];       // inj pairs, fp16
__device__ float    g_dec[Mm];
__device__ float4   g_agg[(size_t)Bb * NCH * Pp];
__device__ float2   g_hst[(size_t)Bb * NCH * Pp];

// ---------------- helpers ----------------
__device__ __forceinline__ uint32_t smem_u32(const void* p) {
    uint32_t a;
    asm("{ .reg .u64 t; cvta.to.shared.u64 t, %1; cvt.u32.u64 %0, t; }" : "=r"(a) : "l"(p));
    return a;
}
#define SWZ(off) ((off) ^ (((off) >> 3) & 0x70))

#define MBAR_INIT(a, n) \
    asm volatile("mbarrier.init.shared.b64 [%0], %1;" :: "r"(a), "r"(n) : "memory")
#define MBAR_EXPECT_TX(a, tx) \
    asm volatile("mbarrier.arrive.expect_tx.shared.b64 _, [%0], %1;" :: "r"(a), "r"(tx) : "memory")
#define MBAR_WAIT(a, ph) do {                                                         \
    asm volatile("{\n\t.reg .pred P1;\n\t"                                            \
        "WAIT_%=:\n\t"                                                                \
        "mbarrier.try_wait.parity.acquire.cta.shared::cta.b64 P1, [%0], %1, 0x989680;\n\t" \
        "@P1 bra.uni DONE_%=;\n\t"                                                    \
        "bra.uni WAIT_%=;\n\t"                                                        \
        "DONE_%=:\n\t}"                                                               \
        :: "r"(a), "r"(ph) : "memory");                                               \
} while (0)
#define BULK_G2S(dst, src, bytes, mbar)                                               \
    asm volatile("cp.async.bulk.shared::cta.global.mbarrier::complete_tx::bytes "     \
                 "[%0], [%1], %2, [%3];"                                              \
                 :: "r"(dst), "l"(src), "r"(bytes), "r"(mbar) : "memory")

__device__ __forceinline__ void ldsm_x4(uint32_t* r, uint32_t addr) {
    asm volatile("ldmatrix.sync.aligned.m8n8.x4.shared.b16 {%0,%1,%2,%3}, [%4];"
                 : "=r"(r[0]), "=r"(r[1]), "=r"(r[2]), "=r"(r[3]) : "r"(addr));
}

#define MMA_F16(C, A, B0, B1)                                                    \
    asm volatile("mma.sync.aligned.m16n8k16.row.col.f32.f16.f16.f32 "            \
                 "{%0,%1,%2,%3}, {%4,%5,%6,%7}, {%8,%9}, {%0,%1,%2,%3};\n"       \
                 : "+f"((C)[0]), "+f"((C)[1]), "+f"((C)[2]), "+f"((C)[3])        \
                 : "r"((A)[0]), "r"((A)[1]), "r"((A)[2]), "r"((A)[3]),           \
                   "r"(B0), "r"(B1))

// ---------------- fast sincos (FMA pipe, no MUFU) ----------------
__device__ __forceinline__ void fsincos(float a, float& s, float& c) {
    float n = rintf(a * 0.6366197723675814f);
    int q = (int)n;
    float r = fmaf(n, -1.5707963705062866f, a);
    r = fmaf(n, 4.3711388e-8f, r);
    float r2 = r * r;
    float sp = r * fmaf(r2, fmaf(r2, fmaf(r2, -1.9841270e-4f, 8.3333338e-3f),
                                  -1.6666667e-1f), 1.0f);
    float cp = fmaf(r2, fmaf(r2, fmaf(r2, -1.3888889e-3f, 4.1666668e-2f), -0.5f), 1.0f);
    bool swap = q & 1;
    float ss = swap ? cp : sp;
    float cc = swap ? sp : cp;
    if (q & 2) ss = -ss;
    if ((q + 1) & 2) cc = -cc;
    s = ss; c = cc;
}

// ---------------- prep: Wh fp16 -> tiled pre-swizzled g_Bt, bias ----------------
__global__ void prep_kernel(const float* __restrict__ Wa, const float* __restrict__ ba,
                            const float* __restrict__ Wi, const float* __restrict__ bi) {
    int n = blockIdx.y;
    int k = blockIdx.x * 256 + threadIdx.x;
    float w = (n < 256) ? Wa[k * 256 + n] : Wi[k * 512 + (n - 256)];
    int nt = n >> 7, r = n & 127, kc = k >> 6, cc = k & 63;
    uint32_t off = SWZ((uint32_t)(r * 128 + cc * 2));
    *(__half*)(g_Bt + ((size_t)(nt * NCHUNK + kc)) * CHUNK_BYTES + off) = __float2half_rn(w);
    if (blockIdx.x == 0 && threadIdx.x == 0)
        g_bcat[n] = (n < 256) ? ba[n] : bi[n - 256];
}

// ---------------- conv: X -> fp16 tiled pre-swizzled g_At, fused decay GEMV ----------------
__global__ __launch_bounds__(256) void conv_kernel(const float* __restrict__ X,
                                                   const float* __restrict__ Wd,
                                                   const float* __restrict__ bd) {
    int wid = threadIdx.x >> 5, lane = threadIdx.x & 31;
    size_t row = (size_t)blockIdx.x * 8 + wid;
    const int mt = (int)(row >> 7), r = (int)(row & 127);
    const float4* xp = (const float4*)(X + row * Kx);
    const float4* wp = (const float4*)Wd;
    float acc = 0.f;
    #pragma unroll
    for (int j = 0; j < 2; j++) {
        int e = j * 64 + lane * 2;
        float4 v0 = xp[e], v1 = xp[e + 1];
        float4 w0 = wp[e], w1 = wp[e + 1];
        acc = fmaf(v0.x, w0.x, fmaf(v0.y, w0.y, fmaf(v0.z, w0.z, fmaf(v0.w, w0.w, acc))));
        acc = fmaf(v1.x, w1.x, fmaf(v1.y, w1.y, fmaf(v1.z, w1.z, fmaf(v1.w, w1.w, acc))));
        __half2 h0 = __floats2half2_rn(v0.x, v0.y);
        __half2 h1 = __floats2half2_rn(v0.z, v0.w);
        __half2 h2 = __floats2half2_rn(v1.x, v1.y);
        __half2 h3 = __floats2half2_rn(v1.z, v1.w);
        uint4 pk;
        pk.x = *(uint32_t*)&h0; pk.y = *(uint32_t*)&h1;
        pk.z = *(uint32_t*)&h2; pk.w = *(uint32_t*)&h3;
        int col = e * 4;
        int kc = col >> 6, cc = col & 63;
        uint32_t off = SWZ((uint32_t)(r * 128 + cc * 2));
        *(uint4*)(g_At + ((size_t)(mt * NCHUNK + kc)) * CHUNK_BYTES + off) = pk;
    }
    #pragma unroll
    for (int o = 16; o; o >>= 1) acc += __shfl_xor_sync(0xffffffffu, acc, o);
    if (!lane) g_dec[row] = 1.f / (1.f + __expf(-(acc + bd[0])));
}

// ---------------- GEMM: persistent CTAs, continuous bulk-copy pipeline ----------------
__global__ __launch_bounds__(NTHREADS, 2) void gemm_kernel() {
    extern __shared__ char dyn[];
    const uint32_t dbase = smem_u32(dyn);
    __shared__ __align__(8) uint64_t s_bar[NSTAGES];

    const int tid  = threadIdx.x;
    const int warp = tid >> 5;
    const int lane = tid & 31;
    const int g    = lane >> 2;
    const int q    = lane & 3;
    const int wm   = (warp & 1) * 64;
    const int wn   = (warp >> 1) * 32;
    const uint32_t barA = smem_u32(s_bar);

    const int cta  = blockIdx.x;
    const int G    = gridDim.x;
    const int base = NTILES / G;
    const int rem  = NTILES - base * G;
    const int ntiles = base + (cta < rem ? 1 : 0);
    const int nlc  = ntiles * NCHUNK;        // total local chunks

    if (tid == 0) {
        #pragma unroll
        for (int s = 0; s < NSTAGES; s++) MBAR_INIT(barA + 8 * s, 1);
    }
    __syncthreads();

    auto issue = [&](int lc) {
        const int gt = cta + (lc >> 3) * G;   // global tile
        const int bm = gt / NNT;
        const int bn = gt - bm * NNT;
        const int c  = lc & 7;
        const int s  = lc % NSTAGES;
        const uint32_t bar = barA + 8 * s;
        MBAR_EXPECT_TX(bar, STAGE_BYTES);
        uint32_t dstA = dbase + s * STAGE_BYTES;
        BULK_G2S(dstA, g_At + ((size_t)(bm * NCHUNK + c)) * CHUNK_BYTES, CHUNK_BYTES, bar);
        BULK_G2S(dstA + A_BYTES, g_Bt + ((size_t)(bn * NCHUNK + c)) * CHUNK_BYTES, CHUNK_BYTES, bar);
    };

    if (tid == 0 && nlc > 0) { issue(0); if (nlc > 1) issue(1); }

    float acc[4][4][4] = {};
    int ph[NSTAGES] = {0, 0, 0};

    const int a_r  = lane & 15;
    const int a_kh = (lane >> 4) * 16;
    const int b_n  = lane & 15;
    const int b_kh = (lane >> 4) * 16;

    for (int lc = 0; lc < nlc; ++lc) {
        const int s = lc % NSTAGES;
        MBAR_WAIT(barA + 8 * s, ph[s]);
        ph[s] ^= 1;
        __syncthreads();
        if (lc + 2 < nlc && tid == 0) issue(lc + 2);

        const uint32_t stA = dbase + s * STAGE_BYTES;
        const uint32_t stB = stA + A_BYTES;

        #pragma unroll
        for (int ks = 0; ks < 4; ks++) {
            uint32_t bf[4][2];
            #pragma unroll
            for (int h = 0; h < 2; h++) {
                uint32_t r[4];
                uint32_t off = (uint32_t)((wn + h * 16 + b_n) * 128 + ks * 32 + b_kh);
                ldsm_x4(r, stB + SWZ(off));
                bf[h * 2 + 0][0] = r[0]; bf[h * 2 + 0][1] = r[2];
                bf[h * 2 + 1][0] = r[1]; bf[h * 2 + 1][1] = r[3];
            }
            #pragma unroll
            for (int mi = 0; mi < 4; mi++) {
                uint32_t af[4];
                uint32_t off = (uint32_t)((wm + mi * 16 + a_r) * 128 + ks * 32 + a_kh);
                ldsm_x4(af, stA + SWZ(off));
                #pragma unroll
                for (int ni = 0; ni < 4; ni++)
                    MMA_F16(acc[mi][ni], af, bf[ni][0], bf[ni][1]);
            }
        }

        // ---- end of tile: epilogue (overlaps in-flight bulk copies of next tile) ----
        if ((lc & 7) == 7) {
            const int gt = cta + (lc >> 3) * G;
            const int bm = gt / NNT;
            const int bn = gt - bm * NNT;
            const int m0 = bm * TILE_M;
            const int n0 = bn * TILE_N;
            const bool is_angle = (n0 < 256);
            #pragma unroll
            for (int mi = 0; mi < 4; mi++) {
                const int r0 = m0 + wm + mi * 16 + g;
                #pragma unroll
                for (int ni = 0; ni < 4; ni++) {
                    const int col = wn + ni * 8 + 2 * q;
                    const float b0 = g_bcat[n0 + col];
                    const float b1 = g_bcat[n0 + col + 1];
                    float v0 = acc[mi][ni][0] + b0;
                    float v1 = acc[mi][ni][1] + b1;
                    float v2 = acc[mi][ni][2] + b0;
                    float v3 = acc[mi][ni][3] + b1;
                    if (is_angle) {
                        const int pc = n0 + col;
                        float s0, c0, s1, c1, s2, c2, s3, c3;
                        fsincos(v0, s0, c0); fsincos(v1, s1, c1);
                        fsincos(v2, s2, c2); fsincos(v3, s3, c3);
                        uint2 w0, w1;
                        __half2 h00 = __floats2half2_rn(c0, s0);
                        __half2 h01 = __floats2half2_rn(c1, s1);
                        __half2 h10 = __floats2half2_rn(c2, s2);
                        __half2 h11 = __floats2half2_rn(c3, s3);
                        w0.x = *(uint32_t*)&h00; w0.y = *(uint32_t*)&h01;
                        w1.x = *(uint32_t*)&h10; w1.y = *(uint32_t*)&h11;
                        *(uint2*)(&g_cs[(size_t)r0 * Pp + pc])       = w0;
                        *(uint2*)(&g_cs[(size_t)(r0 + 8) * Pp + pc]) = w1;
                    } else {
                        const int pu = (n0 - 256 + col) >> 1;
                        g_u[(size_t)r0 * Pp + pu]       = __floats2half2_rn(v0, v1);
                        g_u[(size_t)(r0 + 8) * Pp + pu] = __floats2half2_rn(v2, v3);
                    }
                    acc[mi][ni][0] = 0.f; acc[mi][ni][1] = 0.f;
                    acc[mi][ni][2] = 0.f; acc[mi][ni][3] = 0.f;
                }
            }
        }
    }
}

// ---------------- parallel scan (3 passes) — measured-best config ----------------
__global__ __launch_bounds__(256) void scanA_kernel() {
    const int p     = threadIdx.x;
    const int chunk = blockIdx.x;
    const int b     = blockIdx.y;
    const int t0    = chunk * SCHUNK;

    __shared__ float sd[SCHUNK];
    if (p < SCHUNK) sd[p] = g_dec[b * Tt + t0 + p];
    __syncthreads();

    const __half2* cp = g_cs + ((size_t)b * Tt + t0) * Pp + p;
    const __half2* up = g_u  + ((size_t)b * Tt + t0) * Pp + p;

    float Zr = 1.f, Zi = 0.f, hr = 0.f, hi = 0.f;
    #pragma unroll 4
    for (int j = 0; j < SCHUNK; j++) {
        float2 cs = __half22float2(cp[(size_t)j * Pp]);
        float2 u  = __half22float2(up[(size_t)j * Pp]);
        float d = sd[j];
        float zr = d * cs.x, zi = d * cs.y;
        float nhr = fmaf(zr, hr, fmaf(-zi, hi, u.x));
        float nhi = fmaf(zr, hi, fmaf( zi, hr, u.y));
        hr = nhr; hi = nhi;
        float nZr = zr * Zr - zi * Zi;
        float nZi = fmaf(zr, Zi, zi * Zr);
        Zr = nZr; Zi = nZi;
    }
    g_agg[((size_t)b * NCH + chunk) * Pp + p] = make_float4(Zr, Zi, hr, hi);
}

__global__ __launch_bounds__(256) void scanB_kernel() {
    const int gid = blockIdx.x * 256 + threadIdx.x;
    const int b = gid >> 8, p = gid & 255;
    const size_t base = (size_t)b * NCH * Pp + p;
    float hr = 0.f, hi = 0.f;
    for (int c0 = 0; c0 < NCH; c0 += 8) {
        float4 a[8];
        #pragma unroll
        for (int i = 0; i < 8; i++) a[i] = g_agg[base + (size_t)(c0 + i) * Pp];
        #pragma unroll
        for (int i = 0; i < 8; i++) {
            g_hst[base + (size_t)(c0 + i) * Pp] = make_float2(hr, hi);
            float nhr = fmaf(a[i].x, hr, fmaf(-a[i].y, hi, a[i].z));
            float nhi = fmaf(a[i].x, hi, fmaf( a[i].y, hr, a[i].w));
            hr = nhr; hi = nhi;
        }
    }
}

__global__ __launch_bounds__(256) void scanC_kernel(float* __restrict__ out) {
    const int p     = threadIdx.x;
    const int chunk = blockIdx.x;
    const int b     = blockIdx.y;
    const int t0    = chunk * SCHUNK;

    __shared__ float sd[SCHUNK];
    if (p < SCHUNK) sd[p] = g_dec[b * Tt + t0 + p];
    __syncthreads();

    const __half2* cp = g_cs + ((size_t)b * Tt + t0) * Pp + p;
    const __half2* up = g_u  + ((size_t)b * Tt + t0) * Pp + p;
    float2*        op = (float2*)out + ((size_t)b * Tt + t0) * Pp + p;

    float2 h0 = g_hst[((size_t)b * NCH + chunk) * Pp + p];
    float hr = h0.x, hi = h0.y;
    #pragma unroll 4
    for (int j = 0; j < SCHUNK; j++) {
        float2 cs = __half22float2(cp[(size_t)j * Pp]);
        float2 u  = __half22float2(up[(size_t)j * Pp]);
        float d = sd[j];
        float zr = d * cs.x, zi = d * cs.y;
        float nhr = fmaf(zr, hr, fmaf(-zi, hi, u.x));
        float nhi = fmaf(zr, hi, fmaf( zi, hr, u.y));
        hr = nhr; hi = nhi;
        op[(size_t)j * Pp] = make_float2(hr, hi);
    }
}

// ---------------- launch ----------------
extern "C" void kernel_launch(void* const* d_in, const int* in_sizes, int n_in,
                              void* d_out, int out_size) {
    const float* x  = (const float*)d_in[0];
    const float* Wa = (const float*)d_in[1];
    const float* ba = (const float*)d_in[2];
    const float* Wd = (const float*)d_in[3];
    const float* bd = (const float*)d_in[4];
    const float* Wi = (const float*)d_in[5];
    const float* bi = (const float*)d_in[6];
    float* out = (float*)d_out;

    int dev = 0, nsm = 148;
    cudaGetDevice(&dev);
    cudaDeviceGetAttribute(&nsm, cudaDevAttrMultiProcessorCount, dev);

    cudaFuncSetAttribute(gemm_kernel, cudaFuncAttributeMaxDynamicSharedMemorySize, DYN_BYTES);

    prep_kernel<<<dim3(Kx / 256, Nn), 256>>>(Wa, ba, Wi, bi);
    conv_kernel<<<Mm / 8, 256>>>(x, Wd, bd);
    gemm_kernel<<<2 * nsm, NTHREADS, DYN_BYTES>>>();
    scanA_kernel<<<dim3(NCH, Bb), 256>>>();
    scanB_kernel<<<Bb, 256>>>();
    scanC_kernel<<<dim3(NCH, Bb), 256>>>(out);
}

// round 15
// speedup vs baseline: 1.0575x; 1.0575x over previous
#include <cuda_runtime.h>
#include <cuda_fp16.h>
#include <cstdint>

// ---------------- problem constants ----------------
#define Bb 8
#define Tt 4096
#define Pp 256
#define Mm 32768
#define Kx 512
#define Nn 768            // angles 256 + inj 512
#define TILE_M 128
#define TILE_N 128
#define NTHREADS 256
#define KC 64             // k-chunk (64 fp16 = 128B rows)
#define NCHUNK (Kx / KC)  // 8
#define NSTAGES 3
#define CHUNK_BYTES 16384               // 128 rows x 128B, pre-swizzled
#define A_BYTES CHUNK_BYTES
#define B_BYTES CHUNK_BYTES
#define STAGE_BYTES (A_BYTES + B_BYTES) // 32768
#define DYN_BYTES (NSTAGES * STAGE_BYTES)   // 98304 -> 2 CTAs/SM
#define NMT (Mm / TILE_M)     // 256 m-tiles
#define NNT (Nn / TILE_N)     // 6 n-tiles

// fused conv+prep block split
#define CONV_BLOCKS (Mm / 8)            // 4096
#define PREP_BLOCKS (2 * Nn)            // 1536 (2 k-halves x 768 n)

// scan chunking
#define SCHUNK 32
#define NCH (Tt / SCHUNK)         // 128

// ---------------- device scratch (no allocation) ----------------
// Tiled, pre-swizzled layouts: [tile][k-chunk][16KB block]
__device__ __align__(128) char g_At[(size_t)NMT * NCHUNK * CHUNK_BYTES];
__device__ __align__(128) char g_Bt[(size_t)NNT * NCHUNK * CHUNK_BYTES];
__device__ float    g_bcat[Nn];
__device__ __half2  g_cs[(size_t)Mm * Pp];      // packed (cos, sin), fp16
__device__ __half2  g_u[(size_t)Mm * Pp];       // inj pairs, fp16
__device__ float    g_dec[Mm];
__device__ float4   g_agg[(size_t)Bb * NCH * Pp];
__device__ float2   g_hst[(size_t)Bb * NCH * Pp];

// ---------------- helpers ----------------
__device__ __forceinline__ uint32_t smem_u32(const void* p) {
    uint32_t a;
    asm("{ .reg .u64 t; cvta.to.shared.u64 t, %1; cvt.u32.u64 %0, t; }" : "=r"(a) : "l"(p));
    return a;
}
#define SWZ(off) ((off) ^ (((off) >> 3) & 0x70))

#define MBAR_INIT(a, n) \
    asm volatile("mbarrier.init.shared.b64 [%0], %1;" :: "r"(a), "r"(n) : "memory")
#define MBAR_EXPECT_TX(a, tx) \
    asm volatile("mbarrier.arrive.expect_tx.shared.b64 _, [%0], %1;" :: "r"(a), "r"(tx) : "memory")
#define MBAR_WAIT(a, ph) do {                                                         \
    asm volatile("{\n\t.reg .pred P1;\n\t"                                            \
        "WAIT_%=:\n\t"                                                                \
        "mbarrier.try_wait.parity.acquire.cta.shared::cta.b64 P1, [%0], %1, 0x989680;\n\t" \
        "@P1 bra.uni DONE_%=;\n\t"                                                    \
        "bra.uni WAIT_%=;\n\t"                                                        \
        "DONE_%=:\n\t}"                                                               \
        :: "r"(a), "r"(ph) : "memory");                                               \
} while (0)
#define BULK_G2S(dst, src, bytes, mbar)                                               \
    asm volatile("cp.async.bulk.shared::cta.global.mbarrier::complete_tx::bytes "     \
                 "[%0], [%1], %2, [%3];"                                              \
                 :: "r"(dst), "l"(src), "r"(bytes), "r"(mbar) : "memory")

__device__ __forceinline__ void ldsm_x4(uint32_t* r, uint32_t addr) {
    asm volatile("ldmatrix.sync.aligned.m8n8.x4.shared.b16 {%0,%1,%2,%3}, [%4];"
                 : "=r"(r[0]), "=r"(r[1]), "=r"(r[2]), "=r"(r[3]) : "r"(addr));
}

#define MMA_F16(C, A, B0, B1)                                                    \
    asm volatile("mma.sync.aligned.m16n8k16.row.col.f32.f16.f16.f32 "            \
                 "{%0,%1,%2,%3}, {%4,%5,%6,%7}, {%8,%9}, {%0,%1,%2,%3};\n"       \
                 : "+f"((C)[0]), "+f"((C)[1]), "+f"((C)[2]), "+f"((C)[3])        \
                 : "r"((A)[0]), "r"((A)[1]), "r"((A)[2]), "r"((A)[3]),           \
                   "r"(B0), "r"(B1))

// ---------------- fast sincos (FMA pipe, no MUFU) ----------------
__device__ __forceinline__ void fsincos(float a, float& s, float& c) {
    float n = rintf(a * 0.6366197723675814f);
    int q = (int)n;
    float r = fmaf(n, -1.5707963705062866f, a);
    r = fmaf(n, 4.3711388e-8f, r);
    float r2 = r * r;
    float sp = r * fmaf(r2, fmaf(r2, fmaf(r2, -1.9841270e-4f, 8.3333338e-3f),
                                  -1.6666667e-1f), 1.0f);
    float cp = fmaf(r2, fmaf(r2, fmaf(r2, -1.3888889e-3f, 4.1666668e-2f), -0.5f), 1.0f);
    bool swap = q & 1;
    float ss = swap ? cp : sp;
    float cc = swap ? sp : cp;
    if (q & 2) ss = -ss;
    if ((q + 1) & 2) cc = -cc;
    s = ss; c = cc;
}

// ---------------- fused conv+prep: no data dependency, one launch ----------------
// Blocks [0, CONV_BLOCKS): conv — X -> fp16 tiled pre-swizzled g_At + decay GEMV.
// Blocks [CONV_BLOCKS, CONV_BLOCKS+PREP_BLOCKS): prep — W -> g_Bt + bias.
__global__ __launch_bounds__(256) void convprep_kernel(const float* __restrict__ X,
                                                       const float* __restrict__ Wa,
                                                       const float* __restrict__ ba,
                                                       const float* __restrict__ Wd,
                                                       const float* __restrict__ bd,
                                                       const float* __restrict__ Wi,
                                                       const float* __restrict__ bi) {
    if (blockIdx.x < CONV_BLOCKS) {
        // ---- conv path ----
        int wid = threadIdx.x >> 5, lane = threadIdx.x & 31;
        size_t row = (size_t)blockIdx.x * 8 + wid;
        const int mt = (int)(row >> 7), r = (int)(row & 127);
        const float4* xp = (const float4*)(X + row * Kx);
        const float4* wp = (const float4*)Wd;
        float acc = 0.f;
        #pragma unroll
        for (int j = 0; j < 2; j++) {
            int e = j * 64 + lane * 2;
            float4 v0 = xp[e], v1 = xp[e + 1];
            float4 w0 = wp[e], w1 = wp[e + 1];
            acc = fmaf(v0.x, w0.x, fmaf(v0.y, w0.y, fmaf(v0.z, w0.z, fmaf(v0.w, w0.w, acc))));
            acc = fmaf(v1.x, w1.x, fmaf(v1.y, w1.y, fmaf(v1.z, w1.z, fmaf(v1.w, w1.w, acc))));
            __half2 h0 = __floats2half2_rn(v0.x, v0.y);
            __half2 h1 = __floats2half2_rn(v0.z, v0.w);
            __half2 h2 = __floats2half2_rn(v1.x, v1.y);
            __half2 h3 = __floats2half2_rn(v1.z, v1.w);
            uint4 pk;
            pk.x = *(uint32_t*)&h0; pk.y = *(uint32_t*)&h1;
            pk.z = *(uint32_t*)&h2; pk.w = *(uint32_t*)&h3;
            int col = e * 4;
            int kc = col >> 6, cc = col & 63;
            uint32_t off = SWZ((uint32_t)(r * 128 + cc * 2));
            *(uint4*)(g_At + ((size_t)(mt * NCHUNK + kc)) * CHUNK_BYTES + off) = pk;
        }
        #pragma unroll
        for (int o = 16; o; o >>= 1) acc += __shfl_xor_sync(0xffffffffu, acc, o);
        if (!lane) g_dec[row] = 1.f / (1.f + __expf(-(acc + bd[0])));
    } else {
        // ---- prep path ----
        int pb = blockIdx.x - CONV_BLOCKS;     // 0..1535
        int kblk = pb & 1;                     // k half
        int n = pb >> 1;                       // 0..767
        int k = kblk * 256 + threadIdx.x;      // 0..511
        float w = (n < 256) ? Wa[k * 256 + n] : Wi[k * 512 + (n - 256)];
        int nt = n >> 7, r = n & 127, kc = k >> 6, cc = k & 63;
        uint32_t off = SWZ((uint32_t)(r * 128 + cc * 2));
        *(__half*)(g_Bt + ((size_t)(nt * NCHUNK + kc)) * CHUNK_BYTES + off) = __float2half_rn(w);
        if (kblk == 0 && threadIdx.x == 0)
            g_bcat[n] = (n < 256) ? ba[n] : bi[n - 256];
    }
}

// ---------------- GEMM: fp16 mma.sync, bulk-copy staging, 3-stage, 2 CTAs/SM ----------------
__global__ __launch_bounds__(NTHREADS, 2) void gemm_kernel() {
    extern __shared__ char dyn[];
    const uint32_t dbase = smem_u32(dyn);
    __shared__ float s_bias[TILE_N];
    __shared__ __align__(8) uint64_t s_bar[NSTAGES];

    const int tid  = threadIdx.x;
    const int warp = tid >> 5;
    const int lane = tid & 31;
    const int g    = lane >> 2;
    const int q    = lane & 3;
    const int bm   = blockIdx.y;
    const int bn   = blockIdx.x;
    const int m0   = bm * TILE_M;
    const int n0   = bn * TILE_N;
    const int wm   = (warp & 1) * 64;
    const int wn   = (warp >> 1) * 32;
    const uint32_t barA = smem_u32(s_bar);

    if (tid < TILE_N) s_bias[tid] = g_bcat[n0 + tid];
    if (tid == 0) {
        #pragma unroll
        for (int s = 0; s < NSTAGES; s++) MBAR_INIT(barA + 8 * s, 1);
    }
    __syncthreads();

    auto issue = [&](int c) {
        const int s = c % NSTAGES;
        const uint32_t bar = barA + 8 * s;
        MBAR_EXPECT_TX(bar, STAGE_BYTES);
        uint32_t dstA = dbase + s * STAGE_BYTES;
        BULK_G2S(dstA, g_At + ((size_t)(bm * NCHUNK + c)) * CHUNK_BYTES, CHUNK_BYTES, bar);
        BULK_G2S(dstA + A_BYTES, g_Bt + ((size_t)(bn * NCHUNK + c)) * CHUNK_BYTES, CHUNK_BYTES, bar);
    };

    if (tid == 0) { issue(0); issue(1); }

    float acc[4][4][4] = {};
    int ph[NSTAGES] = {0, 0, 0};

    const int a_r  = lane & 15;
    const int a_kh = (lane >> 4) * 16;
    const int b_n  = lane & 15;
    const int b_kh = (lane >> 4) * 16;

    for (int c = 0; c < NCHUNK; ++c) {
        const int s = c % NSTAGES;
        MBAR_WAIT(barA + 8 * s, ph[s]);
        ph[s] ^= 1;
        __syncthreads();                      // all threads done with this stage's prior use
        if (c + 2 < NCHUNK && tid == 0) issue(c + 2);

        const uint32_t stA = dbase + s * STAGE_BYTES;
        const uint32_t stB = stA + A_BYTES;

        #pragma unroll
        for (int ks = 0; ks < 4; ks++) {
            uint32_t bf[4][2];
            #pragma unroll
            for (int h = 0; h < 2; h++) {
                uint32_t r[4];
                uint32_t off = (uint32_t)((wn + h * 16 + b_n) * 128 + ks * 32 + b_kh);
                ldsm_x4(r, stB + SWZ(off));
                bf[h * 2 + 0][0] = r[0]; bf[h * 2 + 0][1] = r[2];
                bf[h * 2 + 1][0] = r[1]; bf[h * 2 + 1][1] = r[3];
            }
            #pragma unroll
            for (int mi = 0; mi < 4; mi++) {
                uint32_t af[4];
                uint32_t off = (uint32_t)((wm + mi * 16 + a_r) * 128 + ks * 32 + a_kh);
                ldsm_x4(af, stA + SWZ(off));
                #pragma unroll
                for (int ni = 0; ni < 4; ni++)
                    MMA_F16(acc[mi][ni], af, bf[ni][0], bf[ni][1]);
            }
        }
    }

    // ---- epilogue: n0 < 256 => angles (fsincos -> half2 cs); else inj -> half2 u ----
    const bool is_angle = (n0 < 256);
    #pragma unroll
    for (int mi = 0; mi < 4; mi++) {
        const int r0 = m0 + wm + mi * 16 + g;
        #pragma unroll
        for (int ni = 0; ni < 4; ni++) {
            const int col = wn + ni * 8 + 2 * q;
            const float b0 = s_bias[col], b1 = s_bias[col + 1];
            float v0 = acc[mi][ni][0] + b0;
            float v1 = acc[mi][ni][1] + b1;
            float v2 = acc[mi][ni][2] + b0;
            float v3 = acc[mi][ni][3] + b1;
            if (is_angle) {
                const int pc = n0 + col;
                float s0, c0, s1, c1, s2, c2, s3, c3;
                fsincos(v0, s0, c0); fsincos(v1, s1, c1);
                fsincos(v2, s2, c2); fsincos(v3, s3, c3);
                uint2 w0, w1;
                __half2 h00 = __floats2half2_rn(c0, s0);
                __half2 h01 = __floats2half2_rn(c1, s1);
                __half2 h10 = __floats2half2_rn(c2, s2);
                __half2 h11 = __floats2half2_rn(c3, s3);
                w0.x = *(uint32_t*)&h00; w0.y = *(uint32_t*)&h01;
                w1.x = *(uint32_t*)&h10; w1.y = *(uint32_t*)&h11;
                *(uint2*)(&g_cs[(size_t)r0 * Pp + pc])       = w0;
                *(uint2*)(&g_cs[(size_t)(r0 + 8) * Pp + pc]) = w1;
            } else {
                const int pu = (n0 - 256 + col) >> 1;
                g_u[(size_t)r0 * Pp + pu]       = __floats2half2_rn(v0, v1);
                g_u[(size_t)(r0 + 8) * Pp + pu] = __floats2half2_rn(v2, v3);
            }
        }
    }
}

// ---------------- parallel scan (3 passes) — measured-best config ----------------
__global__ __launch_bounds__(256) void scanA_kernel() {
    const int p     = threadIdx.x;
    const int chunk = blockIdx.x;
    const int b     = blockIdx.y;
    const int t0    = chunk * SCHUNK;

    __shared__ float sd[SCHUNK];
    if (p < SCHUNK) sd[p] = g_dec[b * Tt + t0 + p];
    __syncthreads();

    const __half2* cp = g_cs + ((size_t)b * Tt + t0) * Pp + p;
    const __half2* up = g_u  + ((size_t)b * Tt + t0) * Pp + p;

    float Zr = 1.f, Zi = 0.f, hr = 0.f, hi = 0.f;
    #pragma unroll 4
    for (int j = 0; j < SCHUNK; j++) {
        float2 cs = __half22float2(cp[(size_t)j * Pp]);
        float2 u  = __half22float2(up[(size_t)j * Pp]);
        float d = sd[j];
        float zr = d * cs.x, zi = d * cs.y;
        float nhr = fmaf(zr, hr, fmaf(-zi, hi, u.x));
        float nhi = fmaf(zr, hi, fmaf( zi, hr, u.y));
        hr = nhr; hi = nhi;
        float nZr = zr * Zr - zi * Zi;
        float nZi = fmaf(zr, Zi, zi * Zr);
        Zr = nZr; Zi = nZi;
    }
    g_agg[((size_t)b * NCH + chunk) * Pp + p] = make_float4(Zr, Zi, hr, hi);
}

__global__ __launch_bounds__(256) void scanB_kernel() {
    const int gid = blockIdx.x * 256 + threadIdx.x;
    const int b = gid >> 8, p = gid & 255;
    const size_t base = (size_t)b * NCH * Pp + p;
    float hr = 0.f, hi = 0.f;
    for (int c0 = 0; c0 < NCH; c0 += 8) {
        float4 a[8];
        #pragma unroll
        for (int i = 0; i < 8; i++) a[i] = g_agg[base + (size_t)(c0 + i) * Pp];
        #pragma unroll
        for (int i = 0; i < 8; i++) {
            g_hst[base + (size_t)(c0 + i) * Pp] = make_float2(hr, hi);
            float nhr = fmaf(a[i].x, hr, fmaf(-a[i].y, hi, a[i].z));
            float nhi = fmaf(a[i].x, hi, fmaf( a[i].y, hr, a[i].w));
            hr = nhr; hi = nhi;
        }
    }
}

__global__ __launch_bounds__(256) void scanC_kernel(float* __restrict__ out) {
    const int p     = threadIdx.x;
    const int chunk = blockIdx.x;
    const int b     = blockIdx.y;
    const int t0    = chunk * SCHUNK;

    __shared__ float sd[SCHUNK];
    if (p < SCHUNK) sd[p] = g_dec[b * Tt + t0 + p];
    __syncthreads();

    const __half2* cp = g_cs + ((size_t)b * Tt + t0) * Pp + p;
    const __half2* up = g_u  + ((size_t)b * Tt + t0) * Pp + p;
    float2*        op = (float2*)out + ((size_t)b * Tt + t0) * Pp + p;

    float2 h0 = g_hst[((size_t)b * NCH + chunk) * Pp + p];
    float hr = h0.x, hi = h0.y;
    #pragma unroll 4
    for (int j = 0; j < SCHUNK; j++) {
        float2 cs = __half22float2(cp[(size_t)j * Pp]);
        float2 u  = __half22float2(up[(size_t)j * Pp]);
        float d = sd[j];
        float zr = d * cs.x, zi = d * cs.y;
        float nhr = fmaf(zr, hr, fmaf(-zi, hi, u.x));
        float nhi = fmaf(zr, hi, fmaf( zi, hr, u.y));
        hr = nhr; hi = nhi;
        op[(size_t)j * Pp] = make_float2(hr, hi);
    }
}

// ---------------- launch ----------------
extern "C" void kernel_launch(void* const* d_in, const int* in_sizes, int n_in,
                              void* d_out, int out_size) {
    const float* x  = (const float*)d_in[0];
    const float* Wa = (const float*)d_in[1];
    const float* ba = (const float*)d_in[2];
    const float* Wd = (const float*)d_in[3];
    const float* bd = (const float*)d_in[4];
    const float* Wi = (const float*)d_in[5];
    const float* bi = (const float*)d_in[6];
    float* out = (float*)d_out;

    cudaFuncSetAttribute(gemm_kernel, cudaFuncAttributeMaxDynamicSharedMemorySize, DYN_BYTES);

    convprep_kernel<<<CONV_BLOCKS + PREP_BLOCKS, 256>>>(x, Wa, ba, Wd, bd, Wi, bi);
    gemm_kernel<<<dim3(NNT, NMT), NTHREADS, DYN_BYTES>>>();
    scanA_kernel<<<dim3(NCH, Bb), 256>>>();
    scanB_kernel<<<Bb, 256>>>();
    scanC_kernel<<<dim3(NCH, Bb), 256>>>(out);
}

// round 16
// speedup vs baseline: 1.0823x; 1.0234x over previous
#include <cuda_runtime.h>
#include <cuda_fp16.h>
#include <cstdint>

// ---------------- problem constants ----------------
#define Bb 8
#define Tt 4096
#define Pp 256
#define Mm 32768
#define Kx 512
#define Nn 768            // angles 256 + inj 512
#define TILE_M 128
#define TILE_N 128
#define NTHREADS 256
#define KC 64             // k-chunk (64 fp16 = 128B rows)
#define NCHUNK (Kx / KC)  // 8
#define NSTAGES 3
#define CHUNK_BYTES 16384               // 128 rows x 128B, pre-swizzled
#define A_BYTES CHUNK_BYTES
#define B_BYTES CHUNK_BYTES
#define STAGE_BYTES (A_BYTES + B_BYTES) // 32768
#define DYN_BYTES (NSTAGES * STAGE_BYTES)   // 98304 -> 2 CTAs/SM
#define NMT (Mm / TILE_M)     // 256 m-tiles
#define NNT (Nn / TILE_N)     // 6 n-tiles

// fused conv+prep block split
#define CONV_BLOCKS (Mm / 8)            // 4096
#define PREP_BLOCKS (2 * Nn)            // 1536

// scan chunking
#define SCHUNK 32
#define NCH (Tt / SCHUNK)         // 128
#define GRP 8                     // chunks per group (scanB hierarchy)
#define NGRP (NCH / GRP)          // 16 groups per chain

// ---------------- device scratch (no allocation) ----------------
__device__ __align__(128) char g_At[(size_t)NMT * NCHUNK * CHUNK_BYTES];
__device__ __align__(128) char g_Bt[(size_t)NNT * NCHUNK * CHUNK_BYTES];
__device__ float    g_bcat[Nn];
__device__ __half2  g_cs[(size_t)Mm * Pp];      // packed (cos, sin), fp16
__device__ __half2  g_u[(size_t)Mm * Pp];       // inj pairs, fp16
__device__ float    g_dec[Mm];
__device__ float4   g_agg[(size_t)Bb * NCH * Pp];
__device__ float2   g_hst[(size_t)Bb * NCH * Pp];
__device__ float4   g_gagg[(size_t)Bb * NGRP * Pp];   // group aggregates
__device__ float2   g_gst[(size_t)Bb * NGRP * Pp];    // group-start states

// ---------------- helpers ----------------
__device__ __forceinline__ uint32_t smem_u32(const void* p) {
    uint32_t a;
    asm("{ .reg .u64 t; cvta.to.shared.u64 t, %1; cvt.u32.u64 %0, t; }" : "=r"(a) : "l"(p));
    return a;
}
#define SWZ(off) ((off) ^ (((off) >> 3) & 0x70))

#define MBAR_INIT(a, n) \
    asm volatile("mbarrier.init.shared.b64 [%0], %1;" :: "r"(a), "r"(n) : "memory")
#define MBAR_EXPECT_TX(a, tx) \
    asm volatile("mbarrier.arrive.expect_tx.shared.b64 _, [%0], %1;" :: "r"(a), "r"(tx) : "memory")
#define MBAR_WAIT(a, ph) do {                                                         \
    asm volatile("{\n\t.reg .pred P1;\n\t"                                            \
        "WAIT_%=:\n\t"                                                                \
        "mbarrier.try_wait.parity.acquire.cta.shared::cta.b64 P1, [%0], %1, 0x989680;\n\t" \
        "@P1 bra.uni DONE_%=;\n\t"                                                    \
        "bra.uni WAIT_%=;\n\t"                                                        \
        "DONE_%=:\n\t}"                                                               \
        :: "r"(a), "r"(ph) : "memory");                                               \
} while (0)
#define BULK_G2S(dst, src, bytes, mbar)                                               \
    asm volatile("cp.async.bulk.shared::cta.global.mbarrier::complete_tx::bytes "     \
                 "[%0], [%1], %2, [%3];"                                              \
                 :: "r"(dst), "l"(src), "r"(bytes), "r"(mbar) : "memory")

__device__ __forceinline__ void ldsm_x4(uint32_t* r, uint32_t addr) {
    asm volatile("ldmatrix.sync.aligned.m8n8.x4.shared.b16 {%0,%1,%2,%3}, [%4];"
                 : "=r"(r[0]), "=r"(r[1]), "=r"(r[2]), "=r"(r[3]) : "r"(addr));
}

#define MMA_F16(C, A, B0, B1)                                                    \
    asm volatile("mma.sync.aligned.m16n8k16.row.col.f32.f16.f16.f32 "            \
                 "{%0,%1,%2,%3}, {%4,%5,%6,%7}, {%8,%9}, {%0,%1,%2,%3};\n"       \
                 : "+f"((C)[0]), "+f"((C)[1]), "+f"((C)[2]), "+f"((C)[3])        \
                 : "r"((A)[0]), "r"((A)[1]), "r"((A)[2]), "r"((A)[3]),           \
                   "r"(B0), "r"(B1))

// ---------------- fast sincos (FMA pipe, no MUFU) ----------------
__device__ __forceinline__ void fsincos(float a, float& s, float& c) {
    float n = rintf(a * 0.6366197723675814f);
    int q = (int)n;
    float r = fmaf(n, -1.5707963705062866f, a);
    r = fmaf(n, 4.3711388e-8f, r);
    float r2 = r * r;
    float sp = r * fmaf(r2, fmaf(r2, fmaf(r2, -1.9841270e-4f, 8.3333338e-3f),
                                  -1.6666667e-1f), 1.0f);
    float cp = fmaf(r2, fmaf(r2, fmaf(r2, -1.3888889e-3f, 4.1666668e-2f), -0.5f), 1.0f);
    bool swap = q & 1;
    float ss = swap ? cp : sp;
    float cc = swap ? sp : cp;
    if (q & 2) ss = -ss;
    if ((q + 1) & 2) cc = -cc;
    s = ss; c = cc;
}

// ---------------- fused conv+prep ----------------
__global__ __launch_bounds__(256) void convprep_kernel(const float* __restrict__ X,
                                                       const float* __restrict__ Wa,
                                                       const float* __restrict__ ba,
                                                       const float* __restrict__ Wd,
                                                       const float* __restrict__ bd,
                                                       const float* __restrict__ Wi,
                                                       const float* __restrict__ bi) {
    if (blockIdx.x < CONV_BLOCKS) {
        int wid = threadIdx.x >> 5, lane = threadIdx.x & 31;
        size_t row = (size_t)blockIdx.x * 8 + wid;
        const int mt = (int)(row >> 7), r = (int)(row & 127);
        const float4* xp = (const float4*)(X + row * Kx);
        const float4* wp = (const float4*)Wd;
        float acc = 0.f;
        #pragma unroll
        for (int j = 0; j < 2; j++) {
            int e = j * 64 + lane * 2;
            float4 v0 = xp[e], v1 = xp[e + 1];
            float4 w0 = wp[e], w1 = wp[e + 1];
            acc = fmaf(v0.x, w0.x, fmaf(v0.y, w0.y, fmaf(v0.z, w0.z, fmaf(v0.w, w0.w, acc))));
            acc = fmaf(v1.x, w1.x, fmaf(v1.y, w1.y, fmaf(v1.z, w1.z, fmaf(v1.w, w1.w, acc))));
            __half2 h0 = __floats2half2_rn(v0.x, v0.y);
            __half2 h1 = __floats2half2_rn(v0.z, v0.w);
            __half2 h2 = __floats2half2_rn(v1.x, v1.y);
            __half2 h3 = __floats2half2_rn(v1.z, v1.w);
            uint4 pk;
            pk.x = *(uint32_t*)&h0; pk.y = *(uint32_t*)&h1;
            pk.z = *(uint32_t*)&h2; pk.w = *(uint32_t*)&h3;
            int col = e * 4;
            int kc = col >> 6, cc = col & 63;
            uint32_t off = SWZ((uint32_t)(r * 128 + cc * 2));
            *(uint4*)(g_At + ((size_t)(mt * NCHUNK + kc)) * CHUNK_BYTES + off) = pk;
        }
        #pragma unroll
        for (int o = 16; o; o >>= 1) acc += __shfl_xor_sync(0xffffffffu, acc, o);
        if (!lane) g_dec[row] = 1.f / (1.f + __expf(-(acc + bd[0])));
    } else {
        int pb = blockIdx.x - CONV_BLOCKS;
        int kblk = pb & 1;
        int n = pb >> 1;
        int k = kblk * 256 + threadIdx.x;
        float w = (n < 256) ? Wa[k * 256 + n] : Wi[k * 512 + (n - 256)];
        int nt = n >> 7, r = n & 127, kc = k >> 6, cc = k & 63;
        uint32_t off = SWZ((uint32_t)(r * 128 + cc * 2));
        *(__half*)(g_Bt + ((size_t)(nt * NCHUNK + kc)) * CHUNK_BYTES + off) = __float2half_rn(w);
        if (kblk == 0 && threadIdx.x == 0)
            g_bcat[n] = (n < 256) ? ba[n] : bi[n - 256];
    }
}

// ---------------- GEMM: fp16 mma.sync, bulk-copy staging, 3-stage, 2 CTAs/SM ----------------
__global__ __launch_bounds__(NTHREADS, 2) void gemm_kernel() {
    extern __shared__ char dyn[];
    const uint32_t dbase = smem_u32(dyn);
    __shared__ float s_bias[TILE_N];
    __shared__ __align__(8) uint64_t s_bar[NSTAGES];

    const int tid  = threadIdx.x;
    const int warp = tid >> 5;
    const int lane = tid & 31;
    const int g    = lane >> 2;
    const int q    = lane & 3;
    const int bm   = blockIdx.y;
    const int bn   = blockIdx.x;
    const int m0   = bm * TILE_M;
    const int n0   = bn * TILE_N;
    const int wm   = (warp & 1) * 64;
    const int wn   = (warp >> 1) * 32;
    const uint32_t barA = smem_u32(s_bar);

    if (tid < TILE_N) s_bias[tid] = g_bcat[n0 + tid];
    if (tid == 0) {
        #pragma unroll
        for (int s = 0; s < NSTAGES; s++) MBAR_INIT(barA + 8 * s, 1);
    }
    __syncthreads();

    auto issue = [&](int c) {
        const int s = c % NSTAGES;
        const uint32_t bar = barA + 8 * s;
        MBAR_EXPECT_TX(bar, STAGE_BYTES);
        uint32_t dstA = dbase + s * STAGE_BYTES;
        BULK_G2S(dstA, g_At + ((size_t)(bm * NCHUNK + c)) * CHUNK_BYTES, CHUNK_BYTES, bar);
        BULK_G2S(dstA + A_BYTES, g_Bt + ((size_t)(bn * NCHUNK + c)) * CHUNK_BYTES, CHUNK_BYTES, bar);
    };

    if (tid == 0) { issue(0); issue(1); }

    float acc[4][4][4] = {};
    int ph[NSTAGES] = {0, 0, 0};

    const int a_r  = lane & 15;
    const int a_kh = (lane >> 4) * 16;
    const int b_n  = lane & 15;
    const int b_kh = (lane >> 4) * 16;

    for (int c = 0; c < NCHUNK; ++c) {
        const int s = c % NSTAGES;
        MBAR_WAIT(barA + 8 * s, ph[s]);
        ph[s] ^= 1;
        __syncthreads();
        if (c + 2 < NCHUNK && tid == 0) issue(c + 2);

        const uint32_t stA = dbase + s * STAGE_BYTES;
        const uint32_t stB = stA + A_BYTES;

        #pragma unroll
        for (int ks = 0; ks < 4; ks++) {
            uint32_t bf[4][2];
            #pragma unroll
            for (int h = 0; h < 2; h++) {
                uint32_t r[4];
                uint32_t off = (uint32_t)((wn + h * 16 + b_n) * 128 + ks * 32 + b_kh);
                ldsm_x4(r, stB + SWZ(off));
                bf[h * 2 + 0][0] = r[0]; bf[h * 2 + 0][1] = r[2];
                bf[h * 2 + 1][0] = r[1]; bf[h * 2 + 1][1] = r[3];
            }
            #pragma unroll
            for (int mi = 0; mi < 4; mi++) {
                uint32_t af[4];
                uint32_t off = (uint32_t)((wm + mi * 16 + a_r) * 128 + ks * 32 + a_kh);
                ldsm_x4(af, stA + SWZ(off));
                #pragma unroll
                for (int ni = 0; ni < 4; ni++)
                    MMA_F16(acc[mi][ni], af, bf[ni][0], bf[ni][1]);
            }
        }
    }

    const bool is_angle = (n0 < 256);
    #pragma unroll
    for (int mi = 0; mi < 4; mi++) {
        const int r0 = m0 + wm + mi * 16 + g;
        #pragma unroll
        for (int ni = 0; ni < 4; ni++) {
            const int col = wn + ni * 8 + 2 * q;
            const float b0 = s_bias[col], b1 = s_bias[col + 1];
            float v0 = acc[mi][ni][0] + b0;
            float v1 = acc[mi][ni][1] + b1;
            float v2 = acc[mi][ni][2] + b0;
            float v3 = acc[mi][ni][3] + b1;
            if (is_angle) {
                const int pc = n0 + col;
                float s0, c0, s1, c1, s2, c2, s3, c3;
                fsincos(v0, s0, c0); fsincos(v1, s1, c1);
                fsincos(v2, s2, c2); fsincos(v3, s3, c3);
                uint2 w0, w1;
                __half2 h00 = __floats2half2_rn(c0, s0);
                __half2 h01 = __floats2half2_rn(c1, s1);
                __half2 h10 = __floats2half2_rn(c2, s2);
                __half2 h11 = __floats2half2_rn(c3, s3);
                w0.x = *(uint32_t*)&h00; w0.y = *(uint32_t*)&h01;
                w1.x = *(uint32_t*)&h10; w1.y = *(uint32_t*)&h11;
                *(uint2*)(&g_cs[(size_t)r0 * Pp + pc])       = w0;
                *(uint2*)(&g_cs[(size_t)(r0 + 8) * Pp + pc]) = w1;
            } else {
                const int pu = (n0 - 256 + col) >> 1;
                g_u[(size_t)r0 * Pp + pu]       = __floats2half2_rn(v0, v1);
                g_u[(size_t)(r0 + 8) * Pp + pu] = __floats2half2_rn(v2, v3);
            }
        }
    }
}

// ---------------- parallel scan ----------------
__global__ __launch_bounds__(256) void scanA_kernel() {
    const int p     = threadIdx.x;
    const int chunk = blockIdx.x;
    const int b     = blockIdx.y;
    const int t0    = chunk * SCHUNK;

    __shared__ float sd[SCHUNK];
    if (p < SCHUNK) sd[p] = g_dec[b * Tt + t0 + p];
    __syncthreads();

    const __half2* cp = g_cs + ((size_t)b * Tt + t0) * Pp + p;
    const __half2* up = g_u  + ((size_t)b * Tt + t0) * Pp + p;

    float Zr = 1.f, Zi = 0.f, hr = 0.f, hi = 0.f;
    #pragma unroll 4
    for (int j = 0; j < SCHUNK; j++) {
        float2 cs = __half22float2(cp[(size_t)j * Pp]);
        float2 u  = __half22float2(up[(size_t)j * Pp]);
        float d = sd[j];
        float zr = d * cs.x, zi = d * cs.y;
        float nhr = fmaf(zr, hr, fmaf(-zi, hi, u.x));
        float nhi = fmaf(zr, hi, fmaf( zi, hr, u.y));
        hr = nhr; hi = nhi;
        float nZr = zr * Zr - zi * Zi;
        float nZi = fmaf(zr, Zi, zi * Zr);
        Zr = nZr; Zi = nZi;
    }
    g_agg[((size_t)b * NCH + chunk) * Pp + p] = make_float4(Zr, Zi, hr, hi);
}

// B1: compose 8 chunk aggregates -> group aggregate. 32768 threads.
__global__ __launch_bounds__(256) void scanB1_kernel() {
    const int p   = threadIdx.x;
    const int grp = blockIdx.x;
    const int b   = blockIdx.y;
    const size_t base = ((size_t)b * NCH + grp * GRP) * Pp + p;

    float4 a[GRP];
    #pragma unroll
    for (int i = 0; i < GRP; i++) a[i] = g_agg[base + (size_t)i * Pp];

    float Zr = 1.f, Zi = 0.f, Ur = 0.f, Ui = 0.f;
    #pragma unroll
    for (int i = 0; i < GRP; i++) {
        float nUr = fmaf(a[i].x, Ur, fmaf(-a[i].y, Ui, a[i].z));
        float nUi = fmaf(a[i].x, Ui, fmaf( a[i].y, Ur, a[i].w));
        float nZr = a[i].x * Zr - a[i].y * Zi;
        float nZi = fmaf(a[i].x, Zi, a[i].y * Zr);
        Ur = nUr; Ui = nUi; Zr = nZr; Zi = nZi;
    }
    g_gagg[((size_t)b * NGRP + grp) * Pp + p] = make_float4(Zr, Zi, Ur, Ui);
}

// B2: scan 16 group aggregates per chain -> group-start states. 2048 threads, tiny.
__global__ __launch_bounds__(256) void scanB2_kernel() {
    const int gid = blockIdx.x * 256 + threadIdx.x;
    const int b = gid >> 8, p = gid & 255;
    const size_t base = (size_t)b * NGRP * Pp + p;

    float4 A[NGRP];
    #pragma unroll
    for (int i = 0; i < NGRP; i++) A[i] = g_gagg[base + (size_t)i * Pp];

    float hr = 0.f, hi = 0.f;
    #pragma unroll
    for (int i = 0; i < NGRP; i++) {
        g_gst[base + (size_t)i * Pp] = make_float2(hr, hi);
        float nhr = fmaf(A[i].x, hr, fmaf(-A[i].y, hi, A[i].z));
        float nhi = fmaf(A[i].x, hi, fmaf( A[i].y, hr, A[i].w));
        hr = nhr; hi = nhi;
    }
}

// B3: replay 8 compositions from group-start state, write chunk-start states.
__global__ __launch_bounds__(256) void scanB3_kernel() {
    const int p   = threadIdx.x;
    const int grp = blockIdx.x;
    const int b   = blockIdx.y;
    const size_t base = ((size_t)b * NCH + grp * GRP) * Pp + p;

    float4 a[GRP];
    #pragma unroll
    for (int i = 0; i < GRP; i++) a[i] = g_agg[base + (size_t)i * Pp];

    float2 h0 = g_gst[((size_t)b * NGRP + grp) * Pp + p];
    float hr = h0.x, hi = h0.y;
    #pragma unroll
    for (int i = 0; i < GRP; i++) {
        g_hst[base + (size_t)i * Pp] = make_float2(hr, hi);
        float nhr = fmaf(a[i].x, hr, fmaf(-a[i].y, hi, a[i].z));
        float nhi = fmaf(a[i].x, hi, fmaf( a[i].y, hr, a[i].w));
        hr = nhr; hi = nhi;
    }
}

__global__ __launch_bounds__(256) void scanC_kernel(float* __restrict__ out) {
    const int p     = threadIdx.x;
    const int chunk = blockIdx.x;
    const int b     = blockIdx.y;
    const int t0    = chunk * SCHUNK;

    __shared__ float sd[SCHUNK];
    if (p < SCHUNK) sd[p] = g_dec[b * Tt + t0 + p];
    __syncthreads();

    const __half2* cp = g_cs + ((size_t)b * Tt + t0) * Pp + p;
    const __half2* up = g_u  + ((size_t)b * Tt + t0) * Pp + p;
    float2*        op = (float2*)out + ((size_t)b * Tt + t0) * Pp + p;

    float2 h0 = g_hst[((size_t)b * NCH + chunk) * Pp + p];
    float hr = h0.x, hi = h0.y;
    #pragma unroll 4
    for (int j = 0; j < SCHUNK; j++) {
        float2 cs = __half22float2(cp[(size_t)j * Pp]);
        float2 u  = __half22float2(up[(size_t)j * Pp]);
        float d = sd[j];
        float zr = d * cs.x, zi = d * cs.y;
        float nhr = fmaf(zr, hr, fmaf(-zi, hi, u.x));
        float nhi = fmaf(zr, hi, fmaf( zi, hr, u.y));
        hr = nhr; hi = nhi;
        op[(size_t)j * Pp] = make_float2(hr, hi);
    }
}

// ---------------- launch ----------------
extern "C" void kernel_launch(void* const* d_in, const int* in_sizes, int n_in,
                              void* d_out, int out_size) {
    const float* x  = (const float*)d_in[0];
    const float* Wa = (const float*)d_in[1];
    const float* ba = (const float*)d_in[2];
    const float* Wd = (const float*)d_in[3];
    const float* bd = (const float*)d_in[4];
    const float* Wi = (const float*)d_in[5];
    const float* bi = (const float*)d_in[6];
    float* out = (float*)d_out;

    cudaFuncSetAttribute(gemm_kernel, cudaFuncAttributeMaxDynamicSharedMemorySize, DYN_BYTES);

    convprep_kernel<<<CONV_BLOCKS + PREP_BLOCKS, 256>>>(x, Wa, ba, Wd, bd, Wi, bi);
    gemm_kernel<<<dim3(NNT, NMT), NTHREADS, DYN_BYTES>>>();
    scanA_kernel<<<dim3(NCH, Bb), 256>>>();
    scanB1_kernel<<<dim3(NGRP, Bb), 256>>>();
    scanB2_kernel<<<Bb, 256>>>();
    scanB3_kernel<<<dim3(NGRP, Bb), 256>>>();
    scanC_kernel<<<dim3(NCH, Bb), 256>>>(out);
}